// round 14
// baseline (speedup 1.0000x reference)
#include <cuda_runtime.h>
#include <cstdint>
#include <math.h>

// Scratch for Q, K, V projections: [N=8, C=1024, W=1024] fp32 each.
// Values stored PRESCALED by (1+2^-11) so raw-bit HMMA.tf32 truncation is
// unbiased (statistically equivalent to cvt.rna).
__device__ float g_q[8u * 1024u * 1024u];
__device__ float g_k[8u * 1024u * 1024u];
__device__ float g_v[8u * 1024u * 1024u];
__device__ int   g_done[8];          // per-batch gemm-completion semaphores

static __device__ constexpr float PRESCALE = 1.00048828125f;  // 1 + 2^-11

__device__ __forceinline__ uint32_t f2tf32(float f) {
    uint32_t u;
    asm("cvt.rna.tf32.f32 %0, %1;" : "=r"(u) : "f"(f));
    return u;
}
__device__ __forceinline__ float tf32r(float f) {
    return __uint_as_float(f2tf32(f));
}
__device__ __forceinline__ float ex2(float x) {
    float y;
    asm("ex2.approx.f32 %0, %1;" : "=f"(y) : "f"(x));
    return y;
}

// L1-CACHED async copy (.ca — K/V tiles re-read by 16 CTAs; L1 reuse matters)
#define CP_ASYNC16(dst, src) \
    asm volatile("cp.async.ca.shared.global [%0], [%1], 16;" \
        :: "r"(dst), "l"(src))
#define CP_COMMIT() asm volatile("cp.async.commit_group;" ::: "memory")
#define CP_WAIT0()  asm volatile("cp.async.wait_group 0;" ::: "memory")

__device__ __forceinline__ void mma_tf32_16x8x8(
    float* d, const uint32_t* a, const uint32_t* b)
{
    asm volatile(
        "mma.sync.aligned.m16n8k8.row.col.f32.tf32.tf32.f32 "
        "{%0,%1,%2,%3}, {%4,%5,%6,%7}, {%8,%9}, {%0,%1,%2,%3};"
        : "+f"(d[0]), "+f"(d[1]), "+f"(d[2]), "+f"(d[3])
        : "r"(a[0]), "r"(a[1]), "r"(a[2]), "r"(a[3]),
          "r"(b[0]), "r"(b[1]));
}

// Reset semaphores (runs before the fused kernel every launch/replay)
__global__ void init_sem() {
    if (threadIdx.x < 8) g_done[threadIdx.x] = 0;
}

// ---------------------------------------------------------------------------
// Fused kernel, INTERLEAVED batch-pipelined ordering. 3584 blocks of 128:
//   per batch n, a 448-block group: [192 gemm tiles][256 attn blocks].
//   gemm(n): computes Q/K/V tiles, fence, atomicAdd(g_done[n]).
//   attn(n): spins until g_done[n]==192, then R11 flash attention — running
//            concurrently with gemm(n+1..) groups (true tensor-pipe overlap).
// Deadlock-free: a waiter's dependencies all have lower block indices, and
// CTA dispatch is in-order, so they are resident-or-retired.
// ---------------------------------------------------------------------------
__global__ __launch_bounds__(128, 3) void fused_kernel(
    const float* __restrict__ hs,   const float* __restrict__ mask,
    const float* __restrict__ wq, const float* __restrict__ bq,
    const float* __restrict__ wk, const float* __restrict__ bk,
    const float* __restrict__ wv, const float* __restrict__ bv,
    float* __restrict__ outp)
{
    __shared__ uint32_t smem_u[8960];   // 35840 B overlay

    const int bid = blockIdx.x;
    const int tid = threadIdx.x;
    const int lane = tid & 31;
    const int gid  = lane >> 2;
    const int tig  = lane & 3;

    const int n = bid / 448;      // batch
    const int g = bid % 448;      // slot within batch group

    if (g < 192) {
        // ================= GEMM path =================
        uint32_t* const As = smem_u;            // [128*20]
        uint32_t* const Bs = smem_u + 2560;     // [16*136]

        const int r     = g;
        const int which = r / 64;
        const int by    = (r % 64) / 8;
        const int bx    = r % 8;

        const float* A;
        const float* bias;
        float* out;
        if (which == 0)      { A = wq; bias = bq; out = g_q; }
        else if (which == 1) { A = wk; bias = bk; out = g_k; }
        else                 { A = wv; bias = bv; out = g_v; }

        const float* B = hs + (size_t)n * 1024u * 1024u;
        out += (size_t)n * 1024u * 1024u;

        const int m0 = by * 128;
        const int w0 = bx * 128;

        const int wid = tid >> 5;
        const int wm = wid >> 1;
        const int wn = wid & 1;

        const int a_r = tid >> 2;
        const int a_j = tid & 3;
        const int b_k = tid >> 5;
        const int b_n4 = tid & 31;

        const float* gA = A + (size_t)(m0 + a_r) * 1024 + a_j * 4;
        const float* gB = B + (size_t)b_k * 1024 + w0 + b_n4 * 4;

        float acc[4][8][4];
#pragma unroll
        for (int i = 0; i < 4; i++)
#pragma unroll
            for (int j = 0; j < 8; j++)
#pragma unroll
                for (int u = 0; u < 4; u++) acc[i][j][u] = 0.f;

        float4 areg[4], breg[4];
#pragma unroll
        for (int it = 0; it < 4; it++) {
            areg[it] = *(const float4*)(gA + (size_t)(it * 32) * 1024);
            breg[it] = *(const float4*)(gB + (size_t)(it * 4) * 1024);
        }

        for (int c = 0; c < 64; c++) {
#pragma unroll
            for (int it = 0; it < 4; it++) {
                uint4 ca;
                ca.x = f2tf32(areg[it].x); ca.y = f2tf32(areg[it].y);
                ca.z = f2tf32(areg[it].z); ca.w = f2tf32(areg[it].w);
                *(uint4*)&As[(a_r + it * 32) * 20 + a_j * 4] = ca;
                uint4 cb;
                cb.x = f2tf32(breg[it].x); cb.y = f2tf32(breg[it].y);
                cb.z = f2tf32(breg[it].z); cb.w = f2tf32(breg[it].w);
                *(uint4*)&Bs[(b_k + it * 4) * 136 + b_n4 * 4] = cb;
            }
            __syncthreads();

            if (c < 63) {
                const int k0 = (c + 1) * 16;
#pragma unroll
                for (int it = 0; it < 4; it++) {
                    areg[it] = *(const float4*)(gA + (size_t)(it * 32) * 1024 + k0);
                    breg[it] = *(const float4*)(gB + (size_t)(k0 + it * 4) * 1024);
                }
            }

#pragma unroll
            for (int t = 0; t < 2; t++) {
                uint32_t af[4][4];
#pragma unroll
                for (int i = 0; i < 4; i++) {
                    const int bm = wm * 64 + i * 16;
                    af[i][0] = As[(bm + gid) * 20 + t * 8 + tig];
                    af[i][1] = As[(bm + gid + 8) * 20 + t * 8 + tig];
                    af[i][2] = As[(bm + gid) * 20 + t * 8 + tig + 4];
                    af[i][3] = As[(bm + gid + 8) * 20 + t * 8 + tig + 4];
                }
                uint32_t bf[8][2];
#pragma unroll
                for (int j = 0; j < 8; j++) {
                    const int bn = wn * 64 + j * 8 + gid;
                    bf[j][0] = Bs[(t * 8 + tig) * 136 + bn];
                    bf[j][1] = Bs[(t * 8 + tig + 4) * 136 + bn];
                }
#pragma unroll
                for (int i = 0; i < 4; i++)
#pragma unroll
                    for (int j = 0; j < 8; j++)
                        mma_tf32_16x8x8(acc[i][j], af[i], bf[j]);
            }
            __syncthreads();
        }

#pragma unroll
        for (int i = 0; i < 4; i++) {
            const int row0 = m0 + wm * 64 + i * 16 + gid;
            const int row1 = row0 + 8;
            const float bb0 = bias[row0];
            const float bb1 = bias[row1];
#pragma unroll
            for (int j = 0; j < 8; j++) {
                const int col = w0 + wn * 64 + j * 8 + tig * 2;
                float2 o0, o1;
                o0.x = (acc[i][j][0] + bb0) * PRESCALE;
                o0.y = (acc[i][j][1] + bb0) * PRESCALE;
                o1.x = (acc[i][j][2] + bb1) * PRESCALE;
                o1.y = (acc[i][j][3] + bb1) * PRESCALE;
                *(float2*)&out[(size_t)row0 * 1024 + col] = o0;
                *(float2*)&out[(size_t)row1 * 1024 + col] = o1;
            }
        }

        // Publish: stores visible to other blocks, then count this tile done.
        __threadfence();
        __syncthreads();
        if (tid == 0) atomicAdd(&g_done[n], 1);

    } else {
        // ================= Attention path =================
        uint32_t* const Ks = smem_u;            // [64*72]
        uint32_t* const Vs = smem_u + 4608;     // [64*68]

        const int j  = g - 192;
        const int qt = j % 16;
        const int h  = j / 16;

        // Wait until batch n's 192 gemm tiles are published.
        if (tid == 0) {
            while (atomicAdd(&g_done[n], 0) < 192) __nanosleep(1024);
        }
        __syncthreads();
        __threadfence();   // order semaphore acquire before Q/K/V reads

        const int wm = tid >> 5;

        const size_t base = ((size_t)n * 1024 + (size_t)h * 64) * 1024;
        const float* Qg = g_q + base;
        const float* Kg = g_k + base;
        const float* Vg = g_v + base;
        const int qrow = qt * 64 + wm * 16 + gid;

        const int ld_d  = tid >> 4;
        const int ld_c  = (tid & 15) * 4;
        const uint32_t ks_base = (uint32_t)__cvta_generic_to_shared(Ks);
        const uint32_t vs_base = (uint32_t)__cvta_generic_to_shared(Vs);

        // Prologue: start K(0)
#pragma unroll
        for (int i = 0; i < 8; i++) {
            const int d = i * 8 + ld_d;
            CP_ASYNC16(ks_base + (d * 72 + ld_c) * 4,
                       Kg + (size_t)d * 1024 + ld_c);
        }
        CP_COMMIT();

        uint32_t qa[8][4];
#pragma unroll
        for (int t = 0; t < 8; t++) {
            qa[t][0] = __float_as_uint(Qg[(size_t)(8 * t + tig) * 1024 + qrow]);
            qa[t][1] = __float_as_uint(Qg[(size_t)(8 * t + tig) * 1024 + qrow + 8]);
            qa[t][2] = __float_as_uint(Qg[(size_t)(8 * t + tig + 4) * 1024 + qrow]);
            qa[t][3] = __float_as_uint(Qg[(size_t)(8 * t + tig + 4) * 1024 + qrow + 8]);
        }

        float o[8][4];
#pragma unroll
        for (int jn = 0; jn < 8; jn++)
#pragma unroll
            for (int u = 0; u < 4; u++) o[jn][u] = 0.f;
        float m0 = -1e30f, m1 = -1e30f, l0 = 0.f, l1 = 0.f;
        const float L2E = 1.44269504f;

        for (int kt = 0; kt < 16; kt++) {
            const int k0 = kt * 64;

            CP_WAIT0();
            __syncthreads();

            // Start V(kt)
#pragma unroll
            for (int i = 0; i < 8; i++) {
                const int d = i * 8 + ld_d;
                CP_ASYNC16(vs_base + (d * 68 + ld_c) * 4,
                           Vg + (size_t)d * 1024 + k0 + ld_c);
            }
            CP_COMMIT();

            float s[8][4];
#pragma unroll
            for (int jj = 0; jj < 8; jj++)
#pragma unroll
                for (int u = 0; u < 4; u++) s[jj][u] = 0.f;
#pragma unroll
            for (int t = 0; t < 8; t++) {
#pragma unroll
                for (int jj = 0; jj < 8; jj++) {
                    uint32_t b[2];
                    b[0] = Ks[(8 * t + tig) * 72 + 8 * jj + gid];
                    b[1] = Ks[(8 * t + tig + 4) * 72 + 8 * jj + gid];
                    mma_tf32_16x8x8(s[jj], qa[t], b);
                }
            }

            float mx0 = -1e30f, mx1 = -1e30f;
#pragma unroll
            for (int jj = 0; jj < 8; jj++) {
                float2 mv = *(const float2*)&mask[(size_t)n * 1024 + k0 + 8 * jj + 2 * tig];
                s[jj][0] = fmaf(s[jj][0], 0.125f, mv.x);
                s[jj][1] = fmaf(s[jj][1], 0.125f, mv.y);
                s[jj][2] = fmaf(s[jj][2], 0.125f, mv.x);
                s[jj][3] = fmaf(s[jj][3], 0.125f, mv.y);
                mx0 = fmaxf(mx0, fmaxf(s[jj][0], s[jj][1]));
                mx1 = fmaxf(mx1, fmaxf(s[jj][2], s[jj][3]));
            }
            mx0 = fmaxf(mx0, __shfl_xor_sync(0xffffffffu, mx0, 1));
            mx0 = fmaxf(mx0, __shfl_xor_sync(0xffffffffu, mx0, 2));
            mx1 = fmaxf(mx1, __shfl_xor_sync(0xffffffffu, mx1, 1));
            mx1 = fmaxf(mx1, __shfl_xor_sync(0xffffffffu, mx1, 2));
            const float nm0 = fmaxf(m0, mx0);
            const float nm1 = fmaxf(m1, mx1);
            const float a0 = ex2((m0 - nm0) * L2E);
            const float a1 = ex2((m1 - nm1) * L2E);
            const float c0 = -nm0 * L2E;
            const float c1 = -nm1 * L2E;
            float s0 = 0.f, s1 = 0.f;
#pragma unroll
            for (int jj = 0; jj < 8; jj++) {
                s[jj][0] = tf32r(ex2(fmaf(s[jj][0], L2E, c0)));
                s[jj][1] = tf32r(ex2(fmaf(s[jj][1], L2E, c0)));
                s[jj][2] = tf32r(ex2(fmaf(s[jj][2], L2E, c1)));
                s[jj][3] = tf32r(ex2(fmaf(s[jj][3], L2E, c1)));
                s0 += s[jj][0] + s[jj][1];
                s1 += s[jj][2] + s[jj][3];
            }
            s0 += __shfl_xor_sync(0xffffffffu, s0, 1);
            s0 += __shfl_xor_sync(0xffffffffu, s0, 2);
            s1 += __shfl_xor_sync(0xffffffffu, s1, 1);
            s1 += __shfl_xor_sync(0xffffffffu, s1, 2);
            l0 = l0 * a0 + s0;
            l1 = l1 * a1 + s1;
            m0 = nm0; m1 = nm1;
#pragma unroll
            for (int jn = 0; jn < 8; jn++) {
                o[jn][0] *= a0; o[jn][1] *= a0;
                o[jn][2] *= a1; o[jn][3] *= a1;
            }

            CP_WAIT0();
            __syncthreads();

            if (kt < 15) {
#pragma unroll
                for (int i = 0; i < 8; i++) {
                    const int d = i * 8 + ld_d;
                    CP_ASYNC16(ks_base + (d * 72 + ld_c) * 4,
                               Kg + (size_t)d * 1024 + (k0 + 64) + ld_c);
                }
            }
            CP_COMMIT();

            const int src0 = (lane & 28) | (tig >> 1);
            const int src1 = src0 + 2;
#pragma unroll
            for (int t = 0; t < 8; t++) {
                float x00 = __shfl_sync(0xffffffffu, s[t][0], src0);
                float x01 = __shfl_sync(0xffffffffu, s[t][1], src0);
                float x10 = __shfl_sync(0xffffffffu, s[t][2], src0);
                float x11 = __shfl_sync(0xffffffffu, s[t][3], src0);
                float x20 = __shfl_sync(0xffffffffu, s[t][0], src1);
                float x21 = __shfl_sync(0xffffffffu, s[t][1], src1);
                float x30 = __shfl_sync(0xffffffffu, s[t][2], src1);
                float x31 = __shfl_sync(0xffffffffu, s[t][3], src1);
                uint32_t a[4];
                a[0] = __float_as_uint((tig & 1) ? x01 : x00);
                a[1] = __float_as_uint((tig & 1) ? x11 : x10);
                a[2] = __float_as_uint((tig & 1) ? x21 : x20);
                a[3] = __float_as_uint((tig & 1) ? x31 : x30);
#pragma unroll
                for (int jn = 0; jn < 8; jn++) {
                    uint32_t b[2];
                    b[0] = Vs[(8 * jn + gid) * 68 + 8 * t + tig];
                    b[1] = Vs[(8 * jn + gid) * 68 + 8 * t + tig + 4];
                    mma_tf32_16x8x8(o[jn], a, b);
                }
            }
        }

        const float inv0 = 1.f / l0;
        const float inv1 = 1.f / l1;
        float* Og = outp + base;
#pragma unroll
        for (int jn = 0; jn < 8; jn++) {
            const int d0 = 8 * jn + 2 * tig;
            Og[(size_t)d0 * 1024 + qrow]           = o[jn][0] * inv0;
            Og[(size_t)(d0 + 1) * 1024 + qrow]     = o[jn][1] * inv0;
            Og[(size_t)d0 * 1024 + qrow + 8]       = o[jn][2] * inv1;
            Og[(size_t)(d0 + 1) * 1024 + qrow + 8] = o[jn][3] * inv1;
        }
    }
}

extern "C" void kernel_launch(void* const* d_in, const int* in_sizes, int n_in,
                              void* d_out, int out_size)
{
    (void)in_sizes; (void)n_in; (void)out_size;
    const float* hs   = (const float*)d_in[0];
    const float* mask = (const float*)d_in[1];
    const float* wq   = (const float*)d_in[2];
    const float* bq   = (const float*)d_in[3];
    const float* wk   = (const float*)d_in[4];
    const float* bk   = (const float*)d_in[5];
    const float* wv   = (const float*)d_in[6];
    const float* bv   = (const float*)d_in[7];
    float* out = (float*)d_out;

    init_sem<<<1, 32>>>();
    fused_kernel<<<3584, 128>>>(hs, mask, wq, bq, wk, bk, wv, bv, out);
}

// round 16
// speedup vs baseline: 1.7052x; 1.7052x over previous
#include <cuda_runtime.h>
#include <cstdint>
#include <math.h>

// Scratch for Q, K, V projections: [N=8, C=1024, W=1024] fp32 each.
// Values stored PRESCALED by (1+2^-11) so raw-bit HMMA.tf32 truncation is
// unbiased (statistically equivalent to cvt.rna).
__device__ float g_q[8u * 1024u * 1024u];
__device__ float g_k[8u * 1024u * 1024u];
__device__ float g_v[8u * 1024u * 1024u];

static __device__ constexpr float PRESCALE = 1.00048828125f;  // 1 + 2^-11

__device__ __forceinline__ uint32_t f2tf32(float f) {
    uint32_t u;
    asm("cvt.rna.tf32.f32 %0, %1;" : "=r"(u) : "f"(f));
    return u;
}
__device__ __forceinline__ float tf32r(float f) {
    return __uint_as_float(f2tf32(f));
}
__device__ __forceinline__ float ex2(float x) {
    float y;
    asm("ex2.approx.f32 %0, %1;" : "=f"(y) : "f"(x));
    return y;
}

// L1-CACHED async copy (.ca — K/V tiles re-read by 16 CTAs; L1 reuse matters)
#define CP_ASYNC16(dst, src) \
    asm volatile("cp.async.ca.shared.global [%0], [%1], 16;" \
        :: "r"(dst), "l"(src))
#define CP_COMMIT() asm volatile("cp.async.commit_group;" ::: "memory")
#define CP_WAIT0()  asm volatile("cp.async.wait_group 0;" ::: "memory")

__device__ __forceinline__ void mma_tf32_16x8x8(
    float* d, const uint32_t* a, const uint32_t* b)
{
    asm volatile(
        "mma.sync.aligned.m16n8k8.row.col.f32.tf32.tf32.f32 "
        "{%0,%1,%2,%3}, {%4,%5,%6,%7}, {%8,%9}, {%0,%1,%2,%3};"
        : "+f"(d[0]), "+f"(d[1]), "+f"(d[2]), "+f"(d[3])
        : "r"(a[0]), "r"(a[1]), "r"(a[2]), "r"(a[3]),
          "r"(b[0]), "r"(b[1]));
}

// ldmatrix x4: four 8x8-b16 tiles == two n8k8 tf32 B-fragment pairs.
__device__ __forceinline__ void ldsm_x4(uint32_t* r, uint32_t saddr) {
    asm volatile(
        "ldmatrix.sync.aligned.m8n8.x4.shared.b16 {%0,%1,%2,%3}, [%4];"
        : "=r"(r[0]), "=r"(r[1]), "=r"(r[2]), "=r"(r[3]) : "r"(saddr));
}

// ---------------------------------------------------------------------------
// QKV projection on tensor cores (tf32 mma.sync) — exact R11 (proven 323us).
// ---------------------------------------------------------------------------
__global__ __launch_bounds__(128) void qkv_gemm_tc(
    const float* __restrict__ hs,
    const float* __restrict__ wq, const float* __restrict__ bq,
    const float* __restrict__ wk, const float* __restrict__ bk,
    const float* __restrict__ wv, const float* __restrict__ bv)
{
    __shared__ uint32_t As[128 * 20];
    __shared__ uint32_t Bs[16 * 136];

    const int which = blockIdx.z % 3;
    const int n     = blockIdx.z / 3;

    const float* A;
    const float* bias;
    float* out;
    if (which == 0)      { A = wq; bias = bq; out = g_q; }
    else if (which == 1) { A = wk; bias = bk; out = g_k; }
    else                 { A = wv; bias = bv; out = g_v; }

    const float* B = hs + (size_t)n * 1024u * 1024u;
    out += (size_t)n * 1024u * 1024u;

    const int m0 = blockIdx.y * 128;
    const int w0 = blockIdx.x * 128;

    const int tid = threadIdx.x;
    const int wid = tid >> 5;
    const int lane = tid & 31;
    const int gid = lane >> 2;
    const int tig = lane & 3;
    const int wm = wid >> 1;
    const int wn = wid & 1;

    const int a_r = tid >> 2;
    const int a_j = tid & 3;
    const int b_k = tid >> 5;
    const int b_n4 = tid & 31;

    const float* gA = A + (size_t)(m0 + a_r) * 1024 + a_j * 4;
    const float* gB = B + (size_t)b_k * 1024 + w0 + b_n4 * 4;

    float acc[4][8][4];
#pragma unroll
    for (int i = 0; i < 4; i++)
#pragma unroll
        for (int j = 0; j < 8; j++)
#pragma unroll
            for (int u = 0; u < 4; u++) acc[i][j][u] = 0.f;

    float4 areg[4], breg[4];
#pragma unroll
    for (int it = 0; it < 4; it++) {
        areg[it] = *(const float4*)(gA + (size_t)(it * 32) * 1024);
        breg[it] = *(const float4*)(gB + (size_t)(it * 4) * 1024);
    }

    for (int c = 0; c < 64; c++) {
#pragma unroll
        for (int it = 0; it < 4; it++) {
            uint4 ca;
            ca.x = f2tf32(areg[it].x); ca.y = f2tf32(areg[it].y);
            ca.z = f2tf32(areg[it].z); ca.w = f2tf32(areg[it].w);
            *(uint4*)&As[(a_r + it * 32) * 20 + a_j * 4] = ca;
            uint4 cb;
            cb.x = f2tf32(breg[it].x); cb.y = f2tf32(breg[it].y);
            cb.z = f2tf32(breg[it].z); cb.w = f2tf32(breg[it].w);
            *(uint4*)&Bs[(b_k + it * 4) * 136 + b_n4 * 4] = cb;
        }
        __syncthreads();

        if (c < 63) {
            const int k0 = (c + 1) * 16;
#pragma unroll
            for (int it = 0; it < 4; it++) {
                areg[it] = *(const float4*)(gA + (size_t)(it * 32) * 1024 + k0);
                breg[it] = *(const float4*)(gB + (size_t)(k0 + it * 4) * 1024);
            }
        }

#pragma unroll
        for (int t = 0; t < 2; t++) {
            uint32_t af[4][4];
#pragma unroll
            for (int i = 0; i < 4; i++) {
                const int bm = wm * 64 + i * 16;
                af[i][0] = As[(bm + gid) * 20 + t * 8 + tig];
                af[i][1] = As[(bm + gid + 8) * 20 + t * 8 + tig];
                af[i][2] = As[(bm + gid) * 20 + t * 8 + tig + 4];
                af[i][3] = As[(bm + gid + 8) * 20 + t * 8 + tig + 4];
            }
            uint32_t bf[8][2];
#pragma unroll
            for (int j = 0; j < 8; j++) {
                const int bn = wn * 64 + j * 8 + gid;
                bf[j][0] = Bs[(t * 8 + tig) * 136 + bn];
                bf[j][1] = Bs[(t * 8 + tig + 4) * 136 + bn];
            }
#pragma unroll
            for (int i = 0; i < 4; i++)
#pragma unroll
                for (int j = 0; j < 8; j++)
                    mma_tf32_16x8x8(acc[i][j], af[i], bf[j]);
        }
        __syncthreads();
    }

#pragma unroll
    for (int i = 0; i < 4; i++) {
        const int row0 = m0 + wm * 64 + i * 16 + gid;
        const int row1 = row0 + 8;
        const float bb0 = bias[row0];
        const float bb1 = bias[row1];
#pragma unroll
        for (int j = 0; j < 8; j++) {
            const int col = w0 + wn * 64 + j * 8 + tig * 2;
            float2 o0, o1;
            o0.x = (acc[i][j][0] + bb0) * PRESCALE;
            o0.y = (acc[i][j][1] + bb0) * PRESCALE;
            o1.x = (acc[i][j][2] + bb1) * PRESCALE;
            o1.y = (acc[i][j][3] + bb1) * PRESCALE;
            *(float2*)&out[(size_t)row0 * 1024 + col] = o0;
            *(float2*)&out[(size_t)row1 * 1024 + col] = o1;
        }
    }
}

// ---------------------------------------------------------------------------
// Tensor-core flash attention — EXACT R11 structure (proven 267us), with ONE
// change: PV B-fragments via ldmatrix.x4 on Vs (already [n][k] stride-68,
// ldmatrix-compatible with zero layout change). K path untouched.
// grid: (16 qtiles, 16 h, 8 n), 128 threads, 36KB static smem.
// ---------------------------------------------------------------------------
__global__ __launch_bounds__(128, 3) void attn_tc(
    const float* __restrict__ mask, float* __restrict__ out)
{
    __shared__ uint32_t Ks[64 * 72];   // [d][k] stride 72, conflict-free frags
    __shared__ uint32_t Vs[64 * 68];   // [n][k] stride 68, ldmatrix-ready

    const int qt = blockIdx.x;
    const int h  = blockIdx.y;
    const int n  = blockIdx.z;

    const int tid  = threadIdx.x;
    const int wm   = tid >> 5;
    const int lane = tid & 31;
    const int gid  = lane >> 2;
    const int tig  = lane & 3;

    const size_t base = ((size_t)n * 1024 + (size_t)h * 64) * 1024;
    const float* Qg = g_q + base;
    const float* Kg = g_k + base;
    const float* Vg = g_v + base;
    const int qrow = qt * 64 + wm * 16 + gid;

    // ldmatrix lane geometry: lanes 0-7 -> rows 0-7 col-half 0 (matrix 0),
    // 8-15 -> rows 0-7 half 1 (m1), 16-23 -> rows 8-15 half 0 (m2),
    // 24-31 -> rows 8-15 half 1 (m3).
    const int lrow = (lane & 7) + ((lane >> 4) << 3);
    const int kq   = ((lane >> 3) & 1) << 2;

    const int ld_d  = tid >> 4;        // 0..7 ; rows d = ld_d + 8*i
    const int ld_c  = (tid & 15) * 4;  // float4 col
    const uint32_t ks_base = (uint32_t)__cvta_generic_to_shared(Ks);
    const uint32_t vs_base = (uint32_t)__cvta_generic_to_shared(Vs);

    // Prologue: start K(0)
#pragma unroll
    for (int i = 0; i < 8; i++) {
        const int d = i * 8 + ld_d;
        CP_ASYNC16(ks_base + (d * 72 + ld_c) * 4,
                   Kg + (size_t)d * 1024 + ld_c);
    }
    CP_COMMIT();

    // Q fragments (raw prescaled fp32; HW truncates to tf32 unbiased)
    uint32_t qa[8][4];
#pragma unroll
    for (int t = 0; t < 8; t++) {
        qa[t][0] = __float_as_uint(Qg[(size_t)(8 * t + tig) * 1024 + qrow]);
        qa[t][1] = __float_as_uint(Qg[(size_t)(8 * t + tig) * 1024 + qrow + 8]);
        qa[t][2] = __float_as_uint(Qg[(size_t)(8 * t + tig + 4) * 1024 + qrow]);
        qa[t][3] = __float_as_uint(Qg[(size_t)(8 * t + tig + 4) * 1024 + qrow + 8]);
    }

    float o[8][4];
#pragma unroll
    for (int jn = 0; jn < 8; jn++)
#pragma unroll
        for (int u = 0; u < 4; u++) o[jn][u] = 0.f;
    float m0 = -1e30f, m1 = -1e30f, l0 = 0.f, l1 = 0.f;
    const float L2E = 1.44269504f;

    for (int kt = 0; kt < 16; kt++) {
        const int k0 = kt * 64;

        // K(kt) ready; all warps past PV(kt-1) reads of Vs after this sync.
        CP_WAIT0();
        __syncthreads();

        // Start V(kt) — overlaps the S compute below.
#pragma unroll
        for (int i = 0; i < 8; i++) {
            const int d = i * 8 + ld_d;
            CP_ASYNC16(vs_base + (d * 68 + ld_c) * 4,
                       Vg + (size_t)d * 1024 + k0 + ld_c);
        }
        CP_COMMIT();

        // S = Q^T K : s[j] covers k-cols 8j..8j+7 (R11 scalar-LDS path)
        float s[8][4];
#pragma unroll
        for (int j = 0; j < 8; j++)
#pragma unroll
            for (int u = 0; u < 4; u++) s[j][u] = 0.f;
#pragma unroll
        for (int t = 0; t < 8; t++) {
#pragma unroll
            for (int j = 0; j < 8; j++) {
                uint32_t b[2];
                b[0] = Ks[(8 * t + tig) * 72 + 8 * j + gid];
                b[1] = Ks[(8 * t + tig + 4) * 72 + 8 * j + gid];
                mma_tf32_16x8x8(s[j], qa[t], b);
            }
        }

        // scale + mask + online softmax (rows qrow, qrow+8)
        float mx0 = -1e30f, mx1 = -1e30f;
#pragma unroll
        for (int j = 0; j < 8; j++) {
            float2 mv = *(const float2*)&mask[(size_t)n * 1024 + k0 + 8 * j + 2 * tig];
            s[j][0] = fmaf(s[j][0], 0.125f, mv.x);
            s[j][1] = fmaf(s[j][1], 0.125f, mv.y);
            s[j][2] = fmaf(s[j][2], 0.125f, mv.x);
            s[j][3] = fmaf(s[j][3], 0.125f, mv.y);
            mx0 = fmaxf(mx0, fmaxf(s[j][0], s[j][1]));
            mx1 = fmaxf(mx1, fmaxf(s[j][2], s[j][3]));
        }
        mx0 = fmaxf(mx0, __shfl_xor_sync(0xffffffffu, mx0, 1));
        mx0 = fmaxf(mx0, __shfl_xor_sync(0xffffffffu, mx0, 2));
        mx1 = fmaxf(mx1, __shfl_xor_sync(0xffffffffu, mx1, 1));
        mx1 = fmaxf(mx1, __shfl_xor_sync(0xffffffffu, mx1, 2));
        const float nm0 = fmaxf(m0, mx0);
        const float nm1 = fmaxf(m1, mx1);
        const float a0 = ex2((m0 - nm0) * L2E);
        const float a1 = ex2((m1 - nm1) * L2E);
        const float c0 = -nm0 * L2E;
        const float c1 = -nm1 * L2E;
        float s0 = 0.f, s1 = 0.f;
#pragma unroll
        for (int j = 0; j < 8; j++) {
            s[j][0] = tf32r(ex2(fmaf(s[j][0], L2E, c0)));
            s[j][1] = tf32r(ex2(fmaf(s[j][1], L2E, c0)));
            s[j][2] = tf32r(ex2(fmaf(s[j][2], L2E, c1)));
            s[j][3] = tf32r(ex2(fmaf(s[j][3], L2E, c1)));
            s0 += s[j][0] + s[j][1];
            s1 += s[j][2] + s[j][3];
        }
        s0 += __shfl_xor_sync(0xffffffffu, s0, 1);
        s0 += __shfl_xor_sync(0xffffffffu, s0, 2);
        s1 += __shfl_xor_sync(0xffffffffu, s1, 1);
        s1 += __shfl_xor_sync(0xffffffffu, s1, 2);
        l0 = l0 * a0 + s0;
        l1 = l1 * a1 + s1;
        m0 = nm0; m1 = nm1;
#pragma unroll
        for (int jn = 0; jn < 8; jn++) {
            o[jn][0] *= a0; o[jn][1] *= a0;
            o[jn][2] *= a1; o[jn][3] *= a1;
        }

        // V(kt) ready; all warps past S(kt) reads of Ks after this sync.
        CP_WAIT0();
        __syncthreads();

        // Start K(kt+1) — overlaps the PV compute below.
        if (kt < 15) {
#pragma unroll
            for (int i = 0; i < 8; i++) {
                const int d = i * 8 + ld_d;
                CP_ASYNC16(ks_base + (d * 72 + ld_c) * 4,
                           Kg + (size_t)d * 1024 + (k0 + 64) + ld_c);
            }
        }
        CP_COMMIT();

        // PV: ctx += P * V — B-fragments via ldmatrix.x4 (THE one change).
        const int src0 = (lane & 28) | (tig >> 1);
        const int src1 = src0 + 2;
#pragma unroll
        for (int t = 0; t < 8; t++) {
            float x00 = __shfl_sync(0xffffffffu, s[t][0], src0);
            float x01 = __shfl_sync(0xffffffffu, s[t][1], src0);
            float x10 = __shfl_sync(0xffffffffu, s[t][2], src0);
            float x11 = __shfl_sync(0xffffffffu, s[t][3], src0);
            float x20 = __shfl_sync(0xffffffffu, s[t][0], src1);
            float x21 = __shfl_sync(0xffffffffu, s[t][1], src1);
            float x30 = __shfl_sync(0xffffffffu, s[t][2], src1);
            float x31 = __shfl_sync(0xffffffffu, s[t][3], src1);
            uint32_t a[4];
            a[0] = __float_as_uint((tig & 1) ? x01 : x00);
            a[1] = __float_as_uint((tig & 1) ? x11 : x10);
            a[2] = __float_as_uint((tig & 1) ? x21 : x20);
            a[3] = __float_as_uint((tig & 1) ? x31 : x30);
#pragma unroll
            for (int jp = 0; jp < 4; jp++) {
                uint32_t bfr[4];
                ldsm_x4(bfr, vs_base +
                        (uint32_t)(((16 * jp + lrow) * 68 + 8 * t + kq) * 4));
                mma_tf32_16x8x8(o[2 * jp],     a, bfr);
                mma_tf32_16x8x8(o[2 * jp + 1], a, bfr + 2);
            }
        }
    }

    // Epilogue: normalize + store transposed (out[d][q]).
    const float inv0 = 1.f / l0;
    const float inv1 = 1.f / l1;
    float* Og = out + base;
#pragma unroll
    for (int jn = 0; jn < 8; jn++) {
        const int d0 = 8 * jn + 2 * tig;
        Og[(size_t)d0 * 1024 + qrow]           = o[jn][0] * inv0;
        Og[(size_t)(d0 + 1) * 1024 + qrow]     = o[jn][1] * inv0;
        Og[(size_t)d0 * 1024 + qrow + 8]       = o[jn][2] * inv1;
        Og[(size_t)(d0 + 1) * 1024 + qrow + 8] = o[jn][3] * inv1;
    }
}

extern "C" void kernel_launch(void* const* d_in, const int* in_sizes, int n_in,
                              void* d_out, int out_size)
{
    (void)in_sizes; (void)n_in; (void)out_size;
    const float* hs   = (const float*)d_in[0];
    const float* mask = (const float*)d_in[1];
    const float* wq   = (const float*)d_in[2];
    const float* bq   = (const float*)d_in[3];
    const float* wk   = (const float*)d_in[4];
    const float* bk   = (const float*)d_in[5];
    const float* wv   = (const float*)d_in[6];
    const float* bv   = (const float*)d_in[7];
    float* out = (float*)d_out;

    dim3 g1(8, 8, 24);   // (W/128, O/128, N*3)
    qkv_gemm_tc<<<g1, 128>>>(hs, wq, bq, wk, bk, wv, bv);

    dim3 g2(16, 16, 8);  // (W/64, H, N)
    attn_tc<<<g2, 128>>>(mask, out);
}

// round 17
// speedup vs baseline: 1.7622x; 1.0334x over previous
#include <cuda_runtime.h>
#include <cstdint>
#include <math.h>

// Scratch: g_q, g_v are [N][C][W] (channel-major). g_k is stored TRANSPOSED:
// [N][W][C] (position-major), so attention can cp.async K tiles directly in
// ldmatrix-friendly [kpos][d] layout. All values PRESCALED by (1+2^-11) so
// raw-bit HMMA.tf32 truncation is unbiased (equivalent to cvt.rna).
__device__ float g_q[8u * 1024u * 1024u];
__device__ float g_k[8u * 1024u * 1024u];
__device__ float g_v[8u * 1024u * 1024u];

static __device__ constexpr float PRESCALE = 1.00048828125f;  // 1 + 2^-11

__device__ __forceinline__ uint32_t f2tf32(float f) {
    uint32_t u;
    asm("cvt.rna.tf32.f32 %0, %1;" : "=r"(u) : "f"(f));
    return u;
}
__device__ __forceinline__ float tf32r(float f) {
    return __uint_as_float(f2tf32(f));
}
__device__ __forceinline__ float ex2(float x) {
    float y;
    asm("ex2.approx.f32 %0, %1;" : "=f"(y) : "f"(x));
    return y;
}

// L1-CACHED async copy (.ca — K/V tiles re-read by 16 CTAs; L1 reuse matters)
#define CP_ASYNC16(dst, src) \
    asm volatile("cp.async.ca.shared.global [%0], [%1], 16;" \
        :: "r"(dst), "l"(src))
#define CP_COMMIT() asm volatile("cp.async.commit_group;" ::: "memory")
#define CP_WAIT0()  asm volatile("cp.async.wait_group 0;" ::: "memory")

__device__ __forceinline__ void mma_tf32_16x8x8(
    float* d, const uint32_t* a, const uint32_t* b)
{
    asm volatile(
        "mma.sync.aligned.m16n8k8.row.col.f32.tf32.tf32.f32 "
        "{%0,%1,%2,%3}, {%4,%5,%6,%7}, {%8,%9}, {%0,%1,%2,%3};"
        : "+f"(d[0]), "+f"(d[1]), "+f"(d[2]), "+f"(d[3])
        : "r"(a[0]), "r"(a[1]), "r"(a[2]), "r"(a[3]),
          "r"(b[0]), "r"(b[1]));
}

// ldmatrix x4: four 8x8-b16 tiles == two n8k8 tf32 B-fragment pairs.
__device__ __forceinline__ void ldsm_x4(uint32_t* r, uint32_t saddr) {
    asm volatile(
        "ldmatrix.sync.aligned.m8n8.x4.shared.b16 {%0,%1,%2,%3}, [%4];"
        : "=r"(r[0]), "=r"(r[1]), "=r"(r[2]), "=r"(r[3]) : "r"(saddr));
}

// ---------------------------------------------------------------------------
// QKV projection (tf32 mma.sync) — R11 body; K blocks write TRANSPOSED.
// ---------------------------------------------------------------------------
__global__ __launch_bounds__(128) void qkv_gemm_tc(
    const float* __restrict__ hs,
    const float* __restrict__ wq, const float* __restrict__ bq,
    const float* __restrict__ wk, const float* __restrict__ bk,
    const float* __restrict__ wv, const float* __restrict__ bv)
{
    __shared__ uint32_t As[128 * 20];
    __shared__ uint32_t Bs[16 * 136];

    const int which = blockIdx.z % 3;
    const int n     = blockIdx.z / 3;

    const float* A;
    const float* bias;
    float* out;
    if (which == 0)      { A = wq; bias = bq; out = g_q; }
    else if (which == 1) { A = wk; bias = bk; out = g_k; }
    else                 { A = wv; bias = bv; out = g_v; }

    const float* B = hs + (size_t)n * 1024u * 1024u;
    out += (size_t)n * 1024u * 1024u;

    const int m0 = blockIdx.y * 128;
    const int w0 = blockIdx.x * 128;

    const int tid = threadIdx.x;
    const int wid = tid >> 5;
    const int lane = tid & 31;
    const int gid = lane >> 2;
    const int tig = lane & 3;
    const int wm = wid >> 1;
    const int wn = wid & 1;

    const int a_r = tid >> 2;
    const int a_j = tid & 3;
    const int b_k = tid >> 5;
    const int b_n4 = tid & 31;

    const float* gA = A + (size_t)(m0 + a_r) * 1024 + a_j * 4;
    const float* gB = B + (size_t)b_k * 1024 + w0 + b_n4 * 4;

    float acc[4][8][4];
#pragma unroll
    for (int i = 0; i < 4; i++)
#pragma unroll
        for (int j = 0; j < 8; j++)
#pragma unroll
            for (int u = 0; u < 4; u++) acc[i][j][u] = 0.f;

    float4 areg[4], breg[4];
#pragma unroll
    for (int it = 0; it < 4; it++) {
        areg[it] = *(const float4*)(gA + (size_t)(it * 32) * 1024);
        breg[it] = *(const float4*)(gB + (size_t)(it * 4) * 1024);
    }

    for (int c = 0; c < 64; c++) {
#pragma unroll
        for (int it = 0; it < 4; it++) {
            uint4 ca;
            ca.x = f2tf32(areg[it].x); ca.y = f2tf32(areg[it].y);
            ca.z = f2tf32(areg[it].z); ca.w = f2tf32(areg[it].w);
            *(uint4*)&As[(a_r + it * 32) * 20 + a_j * 4] = ca;
            uint4 cb;
            cb.x = f2tf32(breg[it].x); cb.y = f2tf32(breg[it].y);
            cb.z = f2tf32(breg[it].z); cb.w = f2tf32(breg[it].w);
            *(uint4*)&Bs[(b_k + it * 4) * 136 + b_n4 * 4] = cb;
        }
        __syncthreads();

        if (c < 63) {
            const int k0 = (c + 1) * 16;
#pragma unroll
            for (int it = 0; it < 4; it++) {
                areg[it] = *(const float4*)(gA + (size_t)(it * 32) * 1024 + k0);
                breg[it] = *(const float4*)(gB + (size_t)(k0 + it * 4) * 1024);
            }
        }

#pragma unroll
        for (int t = 0; t < 2; t++) {
            uint32_t af[4][4];
#pragma unroll
            for (int i = 0; i < 4; i++) {
                const int bm = wm * 64 + i * 16;
                af[i][0] = As[(bm + gid) * 20 + t * 8 + tig];
                af[i][1] = As[(bm + gid + 8) * 20 + t * 8 + tig];
                af[i][2] = As[(bm + gid) * 20 + t * 8 + tig + 4];
                af[i][3] = As[(bm + gid + 8) * 20 + t * 8 + tig + 4];
            }
            uint32_t bf[8][2];
#pragma unroll
            for (int j = 0; j < 8; j++) {
                const int bn = wn * 64 + j * 8 + gid;
                bf[j][0] = Bs[(t * 8 + tig) * 136 + bn];
                bf[j][1] = Bs[(t * 8 + tig + 4) * 136 + bn];
            }
#pragma unroll
            for (int i = 0; i < 4; i++)
#pragma unroll
                for (int j = 0; j < 8; j++)
                    mma_tf32_16x8x8(acc[i][j], af[i], bf[j]);
        }
        __syncthreads();
    }

    if (which != 1) {
        // Q/V: channel-major store (unchanged, coalesced float2)
#pragma unroll
        for (int i = 0; i < 4; i++) {
            const int row0 = m0 + wm * 64 + i * 16 + gid;
            const int row1 = row0 + 8;
            const float bb0 = bias[row0];
            const float bb1 = bias[row1];
#pragma unroll
            for (int j = 0; j < 8; j++) {
                const int col = w0 + wn * 64 + j * 8 + tig * 2;
                float2 o0, o1;
                o0.x = (acc[i][j][0] + bb0) * PRESCALE;
                o0.y = (acc[i][j][1] + bb0) * PRESCALE;
                o1.x = (acc[i][j][2] + bb1) * PRESCALE;
                o1.y = (acc[i][j][3] + bb1) * PRESCALE;
                *(float2*)&out[(size_t)row0 * 1024 + col] = o0;
                *(float2*)&out[(size_t)row1 * 1024 + col] = o1;
            }
        }
    } else {
        // K: TRANSPOSED store out[w][c] (position-major; scattered 4B stores,
        // ~4MB total — negligible at DRAM=5%).
#pragma unroll
        for (int i = 0; i < 4; i++) {
            const int row0 = m0 + wm * 64 + i * 16 + gid;
            const int row1 = row0 + 8;
            const float bb0 = bias[row0];
            const float bb1 = bias[row1];
#pragma unroll
            for (int j = 0; j < 8; j++) {
                const int col = w0 + wn * 64 + j * 8 + tig * 2;
                out[(size_t)(col + 0) * 1024 + row0] = (acc[i][j][0] + bb0) * PRESCALE;
                out[(size_t)(col + 1) * 1024 + row0] = (acc[i][j][1] + bb0) * PRESCALE;
                out[(size_t)(col + 0) * 1024 + row1] = (acc[i][j][2] + bb1) * PRESCALE;
                out[(size_t)(col + 1) * 1024 + row1] = (acc[i][j][3] + bb1) * PRESCALE;
            }
        }
    }
}

// ---------------------------------------------------------------------------
// Tensor-core flash attention — R16 structure, with the S path now ALSO on
// ldmatrix: K arrives from g_k in [kpos][d] layout (transposed by the gemm),
// so cp.async lands it n-major and ldsm_x4 serves both S and PV fragments.
// grid: (16 qtiles, 16 h, 8 n), 128 threads, 34.8KB static smem.
// ---------------------------------------------------------------------------
__global__ __launch_bounds__(128, 3) void attn_tc(
    const float* __restrict__ mask, float* __restrict__ out)
{
    __shared__ uint32_t Ks[64 * 68];   // [kpos][d] stride 68, ldmatrix-ready
    __shared__ uint32_t Vs[64 * 68];   // [n][k] stride 68, ldmatrix-ready

    const int qt = blockIdx.x;
    const int h  = blockIdx.y;
    const int n  = blockIdx.z;

    const int tid  = threadIdx.x;
    const int wm   = tid >> 5;
    const int lane = tid & 31;
    const int gid  = lane >> 2;
    const int tig  = lane & 3;

    const size_t base = ((size_t)n * 1024 + (size_t)h * 64) * 1024;
    const float* Qg = g_q + base;
    const float* KgT = g_k + (size_t)n * 1024u * 1024u;   // [w][c] layout
    const float* Vg = g_v + base;
    const int qrow = qt * 64 + wm * 16 + gid;

    // ldmatrix lane geometry
    const int lrow = (lane & 7) + ((lane >> 4) << 3);
    const int kq   = ((lane >> 3) & 1) << 2;

    const int ld_d  = tid >> 4;        // 0..7 ; rows r = ld_d + 8*i
    const int ld_c  = (tid & 15) * 4;  // float4 col
    const uint32_t ks_base = (uint32_t)__cvta_generic_to_shared(Ks);
    const uint32_t vs_base = (uint32_t)__cvta_generic_to_shared(Vs);

    // Prologue: start K(0) — rows are k-positions, cols are d (head h slice)
#pragma unroll
    for (int i = 0; i < 8; i++) {
        const int r = i * 8 + ld_d;
        CP_ASYNC16(ks_base + (r * 68 + ld_c) * 4,
                   KgT + (size_t)r * 1024 + h * 64 + ld_c);
    }
    CP_COMMIT();

    // Q fragments (raw prescaled fp32; HW truncates to tf32 unbiased)
    uint32_t qa[8][4];
#pragma unroll
    for (int t = 0; t < 8; t++) {
        qa[t][0] = __float_as_uint(Qg[(size_t)(8 * t + tig) * 1024 + qrow]);
        qa[t][1] = __float_as_uint(Qg[(size_t)(8 * t + tig) * 1024 + qrow + 8]);
        qa[t][2] = __float_as_uint(Qg[(size_t)(8 * t + tig + 4) * 1024 + qrow]);
        qa[t][3] = __float_as_uint(Qg[(size_t)(8 * t + tig + 4) * 1024 + qrow + 8]);
    }

    float o[8][4];
#pragma unroll
    for (int jn = 0; jn < 8; jn++)
#pragma unroll
        for (int u = 0; u < 4; u++) o[jn][u] = 0.f;
    float m0 = -1e30f, m1 = -1e30f, l0 = 0.f, l1 = 0.f;
    const float L2E = 1.44269504f;

    for (int kt = 0; kt < 16; kt++) {
        const int k0 = kt * 64;

        // K(kt) ready; all warps past PV(kt-1) reads of Vs after this sync.
        CP_WAIT0();
        __syncthreads();

        // Start V(kt) — overlaps the S compute below.
#pragma unroll
        for (int i = 0; i < 8; i++) {
            const int d = i * 8 + ld_d;
            CP_ASYNC16(vs_base + (d * 68 + ld_c) * 4,
                       Vg + (size_t)d * 1024 + k0 + ld_c);
        }
        CP_COMMIT();

        // S = Q^T K via ldmatrix on Ks ([kpos][d], n-major)
        float s[8][4];
#pragma unroll
        for (int j = 0; j < 8; j++)
#pragma unroll
            for (int u = 0; u < 4; u++) s[j][u] = 0.f;
#pragma unroll
        for (int t = 0; t < 8; t++) {
#pragma unroll
            for (int jp = 0; jp < 4; jp++) {
                uint32_t bfr[4];
                ldsm_x4(bfr, ks_base +
                        (uint32_t)(((16 * jp + lrow) * 68 + 8 * t + kq) * 4));
                mma_tf32_16x8x8(s[2 * jp],     qa[t], bfr);
                mma_tf32_16x8x8(s[2 * jp + 1], qa[t], bfr + 2);
            }
        }

        // scale + mask + online softmax (rows qrow, qrow+8)
        float mx0 = -1e30f, mx1 = -1e30f;
#pragma unroll
        for (int j = 0; j < 8; j++) {
            float2 mv = *(const float2*)&mask[(size_t)n * 1024 + k0 + 8 * j + 2 * tig];
            s[j][0] = fmaf(s[j][0], 0.125f, mv.x);
            s[j][1] = fmaf(s[j][1], 0.125f, mv.y);
            s[j][2] = fmaf(s[j][2], 0.125f, mv.x);
            s[j][3] = fmaf(s[j][3], 0.125f, mv.y);
            mx0 = fmaxf(mx0, fmaxf(s[j][0], s[j][1]));
            mx1 = fmaxf(mx1, fmaxf(s[j][2], s[j][3]));
        }
        mx0 = fmaxf(mx0, __shfl_xor_sync(0xffffffffu, mx0, 1));
        mx0 = fmaxf(mx0, __shfl_xor_sync(0xffffffffu, mx0, 2));
        mx1 = fmaxf(mx1, __shfl_xor_sync(0xffffffffu, mx1, 1));
        mx1 = fmaxf(mx1, __shfl_xor_sync(0xffffffffu, mx1, 2));
        const float nm0 = fmaxf(m0, mx0);
        const float nm1 = fmaxf(m1, mx1);
        const float a0 = ex2((m0 - nm0) * L2E);
        const float a1 = ex2((m1 - nm1) * L2E);
        const float c0 = -nm0 * L2E;
        const float c1 = -nm1 * L2E;
        float s0 = 0.f, s1 = 0.f;
#pragma unroll
        for (int j = 0; j < 8; j++) {
            s[j][0] = tf32r(ex2(fmaf(s[j][0], L2E, c0)));
            s[j][1] = tf32r(ex2(fmaf(s[j][1], L2E, c0)));
            s[j][2] = tf32r(ex2(fmaf(s[j][2], L2E, c1)));
            s[j][3] = tf32r(ex2(fmaf(s[j][3], L2E, c1)));
            s0 += s[j][0] + s[j][1];
            s1 += s[j][2] + s[j][3];
        }
        s0 += __shfl_xor_sync(0xffffffffu, s0, 1);
        s0 += __shfl_xor_sync(0xffffffffu, s0, 2);
        s1 += __shfl_xor_sync(0xffffffffu, s1, 1);
        s1 += __shfl_xor_sync(0xffffffffu, s1, 2);
        l0 = l0 * a0 + s0;
        l1 = l1 * a1 + s1;
        m0 = nm0; m1 = nm1;
#pragma unroll
        for (int jn = 0; jn < 8; jn++) {
            o[jn][0] *= a0; o[jn][1] *= a0;
            o[jn][2] *= a1; o[jn][3] *= a1;
        }

        // V(kt) ready; all warps past S(kt) reads of Ks after this sync.
        CP_WAIT0();
        __syncthreads();

        // Start K(kt+1) — overlaps the PV compute below.
        if (kt < 15) {
#pragma unroll
            for (int i = 0; i < 8; i++) {
                const int r = i * 8 + ld_d;
                CP_ASYNC16(ks_base + (r * 68 + ld_c) * 4,
                           KgT + (size_t)(k0 + 64 + r) * 1024 + h * 64 + ld_c);
            }
        }
        CP_COMMIT();

        // PV: ctx += P * V via ldmatrix on Vs (proven in R16).
        const int src0 = (lane & 28) | (tig >> 1);
        const int src1 = src0 + 2;
#pragma unroll
        for (int t = 0; t < 8; t++) {
            float x00 = __shfl_sync(0xffffffffu, s[t][0], src0);
            float x01 = __shfl_sync(0xffffffffu, s[t][1], src0);
            float x10 = __shfl_sync(0xffffffffu, s[t][2], src0);
            float x11 = __shfl_sync(0xffffffffu, s[t][3], src0);
            float x20 = __shfl_sync(0xffffffffu, s[t][0], src1);
            float x21 = __shfl_sync(0xffffffffu, s[t][1], src1);
            float x30 = __shfl_sync(0xffffffffu, s[t][2], src1);
            float x31 = __shfl_sync(0xffffffffu, s[t][3], src1);
            uint32_t a[4];
            a[0] = __float_as_uint((tig & 1) ? x01 : x00);
            a[1] = __float_as_uint((tig & 1) ? x11 : x10);
            a[2] = __float_as_uint((tig & 1) ? x21 : x20);
            a[3] = __float_as_uint((tig & 1) ? x31 : x30);
#pragma unroll
            for (int jp = 0; jp < 4; jp++) {
                uint32_t bfr[4];
                ldsm_x4(bfr, vs_base +
                        (uint32_t)(((16 * jp + lrow) * 68 + 8 * t + kq) * 4));
                mma_tf32_16x8x8(o[2 * jp],     a, bfr);
                mma_tf32_16x8x8(o[2 * jp + 1], a, bfr + 2);
            }
        }
    }

    // Epilogue: normalize + store transposed (out[d][q]).
    const float inv0 = 1.f / l0;
    const float inv1 = 1.f / l1;
    float* Og = out + base;
#pragma unroll
    for (int jn = 0; jn < 8; jn++) {
        const int d0 = 8 * jn + 2 * tig;
        Og[(size_t)d0 * 1024 + qrow]           = o[jn][0] * inv0;
        Og[(size_t)(d0 + 1) * 1024 + qrow]     = o[jn][1] * inv0;
        Og[(size_t)d0 * 1024 + qrow + 8]       = o[jn][2] * inv1;
        Og[(size_t)(d0 + 1) * 1024 + qrow + 8] = o[jn][3] * inv1;
    }
}

extern "C" void kernel_launch(void* const* d_in, const int* in_sizes, int n_in,
                              void* d_out, int out_size)
{
    (void)in_sizes; (void)n_in; (void)out_size;
    const float* hs   = (const float*)d_in[0];
    const float* mask = (const float*)d_in[1];
    const float* wq   = (const float*)d_in[2];
    const float* bq   = (const float*)d_in[3];
    const float* wk   = (const float*)d_in[4];
    const float* bk   = (const float*)d_in[5];
    const float* wv   = (const float*)d_in[6];
    const float* bv   = (const float*)d_in[7];
    float* out = (float*)d_out;

    dim3 g1(8, 8, 24);   // (W/128, O/128, N*3)
    qkv_gemm_tc<<<g1, 128>>>(hs, wq, bq, wk, bk, wv, bv);

    dim3 g2(16, 16, 8);  // (W/64, H, N)
    attn_tc<<<g2, 128>>>(mask, out);
}